// round 4
// baseline (speedup 1.0000x reference)
#include <cuda_runtime.h>
#include <math.h>

// Fused SNN spike layer, streaming popcount filter:
//  L: linear coalesced float4 stream over the block's 26 contiguous rows;
//     per-thread nonzero count per float4 -> shared bytes. No ballots.
//  C: 16-step chunk counts; rigorous overestimate
//     u[t in chunk C] <= sum_d M[d]*cnt[C-d], M[d] = max srm tap over the
//     chunk lag range (derived from srm on device). Refractory kernel <= 0
//     => unflagged rows can never spike.
//  Z: unflagged rows -> linear predicated STG.128 zero-fill.
//  S: flagged rows (~1-2%) -> exact sequential scan, arithmetic identical to
//     the R1/R2 kernels that scored rel_err = 0.

#define T_LEN    300
#define Q4       75            // float4 per row
#define R        26            // rows per block
#define NTH      512
#define NCH16    19            // ceil(300/16)
#define CNTSTR   76            // Q4 + 1 pad (chunk 18 reads q=75 -> 0)
#define CCSTR    20
#define PENDN    16
#define NDELTA   8
#define THETA    10.0f

__global__ __launch_bounds__(NTH, 4)
void snn_stream_kernel(const float* __restrict__ x,
                       const float* __restrict__ srm,
                       const float* __restrict__ refk,
                       float* __restrict__ out,
                       int B, int Ksrm, int Kref)
{
    __shared__ unsigned char cnt4[R * CNTSTR];   // per-float4 nonzero counts
    __shared__ unsigned char cc[R * CCSTR];      // per-16-chunk counts
    __shared__ unsigned char flag[R];
    __shared__ float s_M[NDELTA];
    __shared__ float s_rt[PENDN];

    const int tid  = threadIdx.x;
    const int row0 = blockIdx.x * R;
    const long long g4base = (long long)row0 * Q4;  // block's first float4
    const long long g4tot  = (long long)B * Q4;

    if (tid < R) flag[tid] = 0;
    if (tid < PENDN) {
        float v = 0.0f;
        if (tid + 1 < Kref) v = refk[tid + 1];
        s_rt[tid] = v;
    }
    if (tid < NDELTA) {
        int lo = 16 * tid - 15; if (lo < 0) lo = 0;
        int hi = 16 * tid + 15; if (hi > Ksrm - 1) hi = Ksrm - 1;
        float m = 0.0f;
        for (int k = lo; k <= hi; ++k) m = fmaxf(m, srm[k]);
        s_M[tid] = m;
    }
    // zero count pads (only q==75 matters; cheap to zero all)
    for (int i = tid; i < R * CNTSTR; i += NTH) cnt4[i] = 0;
    __syncthreads();

    // ---- L: linear coalesced load + count (4 independent LDG.128/thread) ----
    const float4* x4 = (const float4*)x;
#pragma unroll
    for (int it = 0; it < (R * Q4 + NTH - 1) / NTH; ++it) {
        const int idx = it * NTH + tid;
        if (idx < R * Q4 && g4base + idx < g4tot) {
            const float4 v = x4[g4base + idx];
            const int r = idx / Q4;
            const int q = idx - r * Q4;
            int c = (v.x != 0.0f) + (v.y != 0.0f)
                  + (v.z != 0.0f) + (v.w != 0.0f);
            cnt4[r * CNTSTR + q] = (unsigned char)c;
        }
    }
    __syncthreads();

    // ---- C1: 16-chunk counts ----
    if (tid < R * NCH16) {
        const int r = tid / NCH16;
        const int c = tid - r * NCH16;
        const unsigned char* b = cnt4 + r * CNTSTR + 4 * c;
        cc[r * CCSTR + c] = (unsigned char)(b[0] + b[1] + b[2] + b[3]);
    }
    __syncthreads();

    // ---- C2: weighted-popcount bound -> row flags ----
    if (tid < R * NCH16) {
        const int r = tid / NCH16;
        const int C = tid - r * NCH16;
        float bsum = 0.0f;
#pragma unroll
        for (int d = 0; d < NDELTA; ++d) {
            const int c = C - d;
            if (c >= 0) bsum = fmaf(s_M[d], (float)cc[r * CCSTR + c], bsum);
        }
        if (bsum >= THETA - 0.02f) flag[r] = 1;   // benign same-value race
    }
    __syncthreads();

    // ---- Z: linear predicated zero-fill (STG.128) ----
    float4* o4 = (float4*)out;
    const float4 z = make_float4(0.f, 0.f, 0.f, 0.f);
#pragma unroll
    for (int it = 0; it < (R * Q4 + NTH - 1) / NTH; ++it) {
        const int idx = it * NTH + tid;
        if (idx < R * Q4 && g4base + idx < g4tot) {
            const int r = idx / Q4;
            if (!flag[r]) o4[g4base + idx] = z;
        }
    }

    // ---- S: exact scan for flagged rows (rare; R1/R2 arithmetic) ----
    if (tid < R && flag[tid] && (row0 + tid) < B) {
        const double f1d = (double)srm[1];
        const double f2d = (double)srm[2];
        const double ddd = f2d / (2.0 * f1d);
        const double Add = f1d / ddd;
        const float dcy = (float)ddd;
        const float Af  = (float)Add;
        const float dK  = exp2f((float)Ksrm * log2f(dcy));
        const float C2  = Af * dK;
        const float C1  = Af * (float)Ksrm * dK;

        const float* xr = x + (size_t)(row0 + tid) * T_LEN;
        float* orow     = out + (size_t)(row0 + tid) * T_LEN;

        float s1 = 0.0f, s2 = 0.0f, s1d = 0.0f, s2d = 0.0f;
        float p[PENDN];
#pragma unroll
        for (int j = 0; j < PENDN; ++j) p[j] = 0.0f;

        for (int t = 0; t < T_LEN; ++t) {
            const float xv = xr[t];                       // exactly 0.0 or 1.0
            const int j2 = t - Ksrm;
            const float xd = (j2 >= 0) ? xr[j2] : 0.0f;

            s2  = dcy * (s2 + s1);
            s1  = fmaf(dcy, s1, xv);
            s2d = dcy * (s2d + s1d);
            s1d = fmaf(dcy, s1d, xd);

            const float u    = fmaf(-C1, s1d, fmaf(-C2, s2d, Af * s2));
            const float ueff = u + p[0];
            const float s    = (ueff >= THETA) ? 1.0f : 0.0f;

#pragma unroll
            for (int j = 0; j < PENDN - 1; ++j) p[j] = fmaf(s, s_rt[j], p[j + 1]);
            p[PENDN - 1] = s * s_rt[PENDN - 1];

            orow[t] = s;
        }
    }
}

extern "C" void kernel_launch(void* const* d_in, const int* in_sizes, int n_in,
                              void* d_out, int out_size)
{
    const float* x    = (const float*)d_in[0];
    const float* srm  = (const float*)d_in[1];
    const float* refk = (const float*)d_in[2];
    float* out        = (float*)d_out;

    const int total = in_sizes[0];
    const int B     = total / T_LEN;
    const int Ksrm  = in_sizes[1];
    const int Kref  = in_sizes[2];

    const int grid = (B + R - 1) / R;
    snn_stream_kernel<<<grid, NTH>>>(x, srm, refk, out, B, Ksrm, Kref);
}

// round 5
// speedup vs baseline: 2.2397x; 2.2397x over previous
#include <cuda_runtime.h>
#include <math.h>

// Fused SNN spike layer, two-stage filtered streaming:
//  L : linear coalesced float4 stream; per-float4 nonzero counts -> shared.
//  C : 16-chunk counts; rigorous overestimate u <= sum_d M[d]*cnt[C-d]
//      (M from actual srm taps). Refractory <= 0 => unflagged never spike.
//  Z : unflagged rows -> linear STG.128 zero-fill.
//  S2: flagged rows (~0.1-2%) -> EXACT truncated-u recurrence (identical FMA
//      sequence to the scan, no pending). max u < theta => u_eff==u before any
//      spike => output exactly zero. Margin-free, bit-exact.
//  S3: rows with max u >= theta (true spikers, ~0) -> full R1/R2 exact scan.

#define T_LEN    300
#define Q4       75
#define R        26
#define NTH      512
#define NCH16    19
#define CNTSTR   76
#define CCSTR    20
#define PENDN    16
#define NDELTA   8
#define THETA    10.0f

__global__ __launch_bounds__(NTH, 4)
void snn_two_stage_kernel(const float* __restrict__ x,
                          const float* __restrict__ srm,
                          const float* __restrict__ refk,
                          float* __restrict__ out,
                          int B, int Ksrm, int Kref)
{
    __shared__ unsigned char cnt4[R * CNTSTR];
    __shared__ unsigned char cc[R * CCSTR];
    __shared__ unsigned char flag[R];
    __shared__ unsigned char list[R];
    __shared__ int nlist;
    __shared__ float s_M[NDELTA];
    __shared__ float s_rt[PENDN];

    const int tid  = threadIdx.x;
    const int row0 = blockIdx.x * R;
    const long long g4base = (long long)row0 * Q4;
    const long long g4tot  = (long long)B * Q4;

    if (tid < R) { flag[tid] = 0; cnt4[tid * CNTSTR + Q4] = 0; }
    if (tid == 0) nlist = 0;
    if (tid < PENDN) {
        float v = 0.0f;
        if (tid + 1 < Kref) v = refk[tid + 1];
        s_rt[tid] = v;
    }
    if (tid < NDELTA) {
        int lo = 16 * tid - 15; if (lo < 0) lo = 0;
        int hi = 16 * tid + 15; if (hi > Ksrm - 1) hi = Ksrm - 1;
        float m = 0.0f;
        for (int k = lo; k <= hi; ++k) m = fmaxf(m, srm[k]);
        s_M[tid] = m;
    }
    __syncthreads();

    // ---- L: linear coalesced load + per-float4 count ----
    const float4* x4 = (const float4*)x;
#pragma unroll
    for (int it = 0; it < (R * Q4 + NTH - 1) / NTH; ++it) {
        const int idx = it * NTH + tid;
        if (idx < R * Q4 && g4base + idx < g4tot) {
            const float4 v = x4[g4base + idx];
            const int r = idx / Q4;
            const int q = idx - r * Q4;
            int c = (v.x != 0.0f) + (v.y != 0.0f)
                  + (v.z != 0.0f) + (v.w != 0.0f);
            cnt4[r * CNTSTR + q] = (unsigned char)c;
        }
    }
    __syncthreads();

    // ---- C1: 16-chunk counts ----
    if (tid < R * NCH16) {
        const int r = tid / NCH16;
        const int c = tid - r * NCH16;
        const unsigned char* b = cnt4 + r * CNTSTR + 4 * c;
        cc[r * CCSTR + c] = (unsigned char)(b[0] + b[1] + b[2] + b[3]);
    }
    __syncthreads();

    // ---- C2: weighted-popcount bound -> row flags ----
    if (tid < R * NCH16) {
        const int r = tid / NCH16;
        const int C = tid - r * NCH16;
        float bsum = 0.0f;
#pragma unroll
        for (int d = 0; d < NDELTA; ++d) {
            const int c = C - d;
            if (c >= 0) bsum = fmaf(s_M[d], (float)cc[r * CCSTR + c], bsum);
        }
        if (bsum >= THETA - 0.02f) flag[r] = 1;   // benign same-value race
    }
    __syncthreads();

    // ---- build flagged-row list ----
    if (tid < R && flag[tid] && (row0 + tid) < B) {
        const int p = atomicAdd(&nlist, 1);
        list[p] = (unsigned char)tid;
    }
    __syncthreads();

    // ---- Z: zero-fill unflagged rows (linear STG.128) ----
    float4* o4 = (float4*)out;
    const float4 z = make_float4(0.f, 0.f, 0.f, 0.f);
#pragma unroll
    for (int it = 0; it < (R * Q4 + NTH - 1) / NTH; ++it) {
        const int idx = it * NTH + tid;
        if (idx < R * Q4 && g4base + idx < g4tot) {
            const int r = idx / Q4;
            if (!flag[r]) o4[g4base + idx] = z;
        }
    }

    // ---- S2/S3: flagged rows only ----
    if (tid < nlist) {
        const int r = list[tid];
        const int rowg = row0 + r;

        // recurrence constants (identical derivation to R1/R2)
        const double f1d = (double)srm[1];
        const double f2d = (double)srm[2];
        const double ddd = f2d / (2.0 * f1d);
        const double Add = f1d / ddd;
        const float dcy = (float)ddd;
        const float Af  = (float)Add;
        const float dK  = exp2f((float)Ksrm * log2f(dcy));
        const float C2c = Af * dK;
        const float C1c = Af * (float)Ksrm * dK;

        const float* xr = x + (size_t)rowg * T_LEN;

        // S2: exact truncated-u max (same FMA sequence as the scan's u)
        float s1 = 0.0f, s2 = 0.0f, s1d = 0.0f, s2d = 0.0f, mx = -1e30f;
        for (int t = 0; t < T_LEN; ++t) {
            const float xv = xr[t];
            const int j2 = t - Ksrm;
            const float xd = (j2 >= 0) ? xr[j2] : 0.0f;
            s2  = dcy * (s2 + s1);
            s1  = fmaf(dcy, s1, xv);
            s2d = dcy * (s2d + s1d);
            s1d = fmaf(dcy, s1d, xd);
            const float u = fmaf(-C1c, s1d, fmaf(-C2c, s2d, Af * s2));
            mx = fmaxf(mx, u);
        }

        float4* orow4 = (float4*)(out + (size_t)rowg * T_LEN);
        if (mx < THETA) {
            // no threshold crossing possible -> exactly zero output
            for (int q = 0; q < Q4; ++q) orow4[q] = z;
        } else {
            // S3: full exact scan (R1/R2 arithmetic; rel_err == 0 twice)
            float* orow = out + (size_t)rowg * T_LEN;
            s1 = s2 = s1d = s2d = 0.0f;
            float p[PENDN];
#pragma unroll
            for (int j = 0; j < PENDN; ++j) p[j] = 0.0f;

            for (int t = 0; t < T_LEN; ++t) {
                const float xv = xr[t];
                const int j2 = t - Ksrm;
                const float xd = (j2 >= 0) ? xr[j2] : 0.0f;

                s2  = dcy * (s2 + s1);
                s1  = fmaf(dcy, s1, xv);
                s2d = dcy * (s2d + s1d);
                s1d = fmaf(dcy, s1d, xd);

                const float u    = fmaf(-C1c, s1d, fmaf(-C2c, s2d, Af * s2));
                const float ueff = u + p[0];
                const float s    = (ueff >= THETA) ? 1.0f : 0.0f;

#pragma unroll
                for (int j = 0; j < PENDN - 1; ++j)
                    p[j] = fmaf(s, s_rt[j], p[j + 1]);
                p[PENDN - 1] = s * s_rt[PENDN - 1];

                orow[t] = s;
            }
        }
    }
}

extern "C" void kernel_launch(void* const* d_in, const int* in_sizes, int n_in,
                              void* d_out, int out_size)
{
    const float* x    = (const float*)d_in[0];
    const float* srm  = (const float*)d_in[1];
    const float* refk = (const float*)d_in[2];
    float* out        = (float*)d_out;

    const int total = in_sizes[0];
    const int B     = total / T_LEN;
    const int Ksrm  = in_sizes[1];
    const int Kref  = in_sizes[2];

    const int grid = (B + R - 1) / R;
    snn_two_stage_kernel<<<grid, NTH>>>(x, srm, refk, out, B, Ksrm, Kref);
}